// round 1
// baseline (speedup 1.0000x reference)
#include <cuda_runtime.h>

#define NUM_EDGES   500000
#define SIZE1       80000
#define SIZE2       80000
#define BATCH       8

// ---------------------------------------------------------------------------
// Init kernel: out[b, r] = eps_b[r]*exp(b_log_var[r]) + b_mean[r]  (bias term),
// and zero any tail elements (the kl scalar in the flattened tuple output).
// ---------------------------------------------------------------------------
__global__ void init_out_kernel(float* __restrict__ out,
                                const float* __restrict__ b_mean,
                                const float* __restrict__ b_log_var,
                                const float* __restrict__ eps_b,
                                int out_size) {
    int idx = blockIdx.x * blockDim.x + threadIdx.x;
    const int total = BATCH * SIZE2;
    if (idx < total) {
        int r = idx % SIZE2;
        out[idx] = fmaf(__ldg(&eps_b[r]), __expf(__ldg(&b_log_var[r])), __ldg(&b_mean[r]));
    } else if (idx < out_size) {
        out[idx] = 0.0f;   // kl = 0
    }
}

// ---------------------------------------------------------------------------
// Edge kernel: one thread per graph edge. Each edge owns a dense 4x4 weight
// block (flat index e*16 + i*4 + j). For each batch b:
//   out[b, dst*4 + j] += sum_i val[i][j] * x[b, src*4 + i]
// where val = eps_w * exp(weight_log_var) + weight_mean.
// rows[e*16] == dst*4, cols[e*16] == src*4 (structure of adjust_indices).
// Output accumulation via vector L2 reduction (red.global.add.v4.f32) since
// the 4 j-outputs are contiguous.
// ---------------------------------------------------------------------------
__global__ void __launch_bounds__(256)
spmm_edge_kernel(const float* __restrict__ x,
                 const float4* __restrict__ w_mean4,
                 const float4* __restrict__ w_lv4,
                 const float4* __restrict__ eps_w4,
                 const int* __restrict__ rows,
                 const int* __restrict__ cols,
                 float* __restrict__ out) {
    int e = blockIdx.x * blockDim.x + threadIdx.x;
    if (e >= NUM_EDGES) return;

    const int base = e * 4;           // float4 index into 16-float block

    // v[i] holds vals for fixed i, j = 0..3 (a float4 across j)
    float4 v[4];
#pragma unroll
    for (int i = 0; i < 4; i++) {
        float4 m  = __ldg(&w_mean4[base + i]);
        float4 lv = __ldg(&w_lv4[base + i]);
        float4 ep = __ldg(&eps_w4[base + i]);
        v[i].x = fmaf(ep.x, __expf(lv.x), m.x);
        v[i].y = fmaf(ep.y, __expf(lv.y), m.y);
        v[i].z = fmaf(ep.z, __expf(lv.z), m.z);
        v[i].w = fmaf(ep.w, __expf(lv.w), m.w);
    }

    const int dst4 = __ldg(&rows[e * 16]);   // dst*4
    const int src4 = __ldg(&cols[e * 16]);   // src*4

#pragma unroll
    for (int b = 0; b < BATCH; b++) {
        // x[b, src*4 + i], i=0..3 -> one 16B load (src4 divisible by 4)
        float4 xv = *reinterpret_cast<const float4*>(x + (size_t)b * SIZE1 + src4);

        float4 acc;
        acc.x = xv.x * v[0].x;
        acc.y = xv.x * v[0].y;
        acc.z = xv.x * v[0].z;
        acc.w = xv.x * v[0].w;
        acc.x = fmaf(xv.y, v[1].x, acc.x);
        acc.y = fmaf(xv.y, v[1].y, acc.y);
        acc.z = fmaf(xv.y, v[1].z, acc.z);
        acc.w = fmaf(xv.y, v[1].w, acc.w);
        acc.x = fmaf(xv.z, v[2].x, acc.x);
        acc.y = fmaf(xv.z, v[2].y, acc.y);
        acc.z = fmaf(xv.z, v[2].z, acc.z);
        acc.w = fmaf(xv.z, v[2].w, acc.w);
        acc.x = fmaf(xv.w, v[3].x, acc.x);
        acc.y = fmaf(xv.w, v[3].y, acc.y);
        acc.z = fmaf(xv.w, v[3].z, acc.z);
        acc.w = fmaf(xv.w, v[3].w, acc.w);

        float* oaddr = out + (size_t)b * SIZE2 + dst4;
        asm volatile("red.global.add.v4.f32 [%0], {%1, %2, %3, %4};"
                     :: "l"(oaddr), "f"(acc.x), "f"(acc.y), "f"(acc.z), "f"(acc.w)
                     : "memory");
    }
}

extern "C" void kernel_launch(void* const* d_in, const int* in_sizes, int n_in,
                              void* d_out, int out_size) {
    const float* x      = (const float*)d_in[0];
    const float* w_mean = (const float*)d_in[1];
    const float* w_lv   = (const float*)d_in[2];
    const float* b_mean = (const float*)d_in[3];
    const float* b_lv   = (const float*)d_in[4];
    const float* eps_w  = (const float*)d_in[5];
    const float* eps_b  = (const float*)d_in[6];
    const int*   rows   = (const int*)d_in[7];
    const int*   cols   = (const int*)d_in[8];
    float* out = (float*)d_out;

    int init_threads = out_size;                       // covers bias + kl tail
    init_out_kernel<<<(init_threads + 255) / 256, 256>>>(out, b_mean, b_lv, eps_b, out_size);

    spmm_edge_kernel<<<(NUM_EDGES + 255) / 256, 256>>>(
        x,
        (const float4*)w_mean, (const float4*)w_lv, (const float4*)eps_w,
        rows, cols, out);
}